// round 10
// baseline (speedup 1.0000x reference)
#include <cuda_runtime.h>
#include <math.h>

#define DIMK 64
#define NN 16
#define BATCH 4096
#define NRELS 33
#define NT 256
#define NITEMS 2
#define GRID (BATCH / NITEMS)

struct PerItem {
    float e1v[NN * DIMK];     // 4 KB
    float xbuf[NN * DIMK];    // 4 KB
    float userv[DIMK];
    float e0v[DIMK];
    float x0[DIMK];
    float x1[DIMK];
    float outf[DIMK];
    float attn[NN * NN];      // 1 KB
    float urel[NRELS + 3];
    float attn0[NN];
    int   e2[NN * NN];        // 1 KB
    int   r2[NN * NN];        // 1 KB
    int   r1[NN];
};

struct Smem {
    PerItem pi[NITEMS];
    float b0[DIMK];
    float b1[DIMK];
};

__device__ __forceinline__ float fsigmoid(float x) {
    return __fdividef(1.0f, 1.0f + __expf(-x));
}

__global__ __launch_bounds__(NT, 7)
void kgnn_kernel(const int* __restrict__ u, const int* __restrict__ v,
                 const int* __restrict__ adj, const int* __restrict__ rel_adj,
                 const float* __restrict__ usr_emb, const float* __restrict__ ent_emb,
                 const float* __restrict__ rel_emb,
                 const float* __restrict__ W0g, const float* __restrict__ b0g,
                 const float* __restrict__ W1g, const float* __restrict__ b1g,
                 float* __restrict__ out)
{
    extern __shared__ char smem_raw[];
    Smem& s = *reinterpret_cast<Smem*>(smem_raw);
    const int tid  = threadIdx.x;
    const int lane = tid & 31;
    const int warp = tid >> 5;
    const int c     = warp * 8 + (lane & 7);  // output column 0..63
    const int kh    = lane >> 3;              // k-quarter 0..3
    const int kbase = kh * 16;
    const bool kh0  = (kh == 0);

    const float4* ent4 = reinterpret_cast<const float4*>(ent_emb);
    const int item0 = blockIdx.x * NITEMS;

    // W0 column-slice in registers, once per CTA
    float Wreg[16];
    #pragma unroll
    for (int kk = 0; kk < 16; ++kk)
        Wreg[kk] = __ldg(W0g + (kbase + kk) * DIMK + c);
    if (tid < DIMK) { s.b0[tid] = b0g[tid]; s.b1[tid] = b1g[tid]; }
    __syncthreads();

    // ---- P1: indices + e1v staging + root vectors + urel (both items) ----
    #pragma unroll
    for (int ii = 0; ii < NITEMS; ++ii) {
        PerItem& p = s.pi[ii];
        const int vv = __ldg(v + item0 + ii);
        const int uu = __ldg(u + item0 + ii);
        const int m = tid >> 4, n = tid & 15;
        const int e1m = __ldg(adj + vv * NN + m);
        p.e2[tid] = __ldg(adj + e1m * NN + n);
        p.r2[tid] = __ldg(rel_adj + e1m * NN + n);
        reinterpret_cast<float4*>(p.e1v)[tid] = __ldg(ent4 + e1m * 16 + n);
        if (tid < 16) {
            p.r1[tid] = __ldg(rel_adj + vv * NN + tid);
            reinterpret_cast<float4*>(p.userv)[tid] = __ldg(
                reinterpret_cast<const float4*>(usr_emb) + uu * 16 + tid);
        } else if (tid < 32) {
            reinterpret_cast<float4*>(p.e0v)[tid - 16] = __ldg(ent4 + vv * 16 + (tid - 16));
        }
        const float ua = __ldg(usr_emb + uu * DIMK + lane);
        const float ub = __ldg(usr_emb + uu * DIMK + lane + 32);
        for (int r = warp; r < NRELS; r += 8) {
            float pp = ua * __ldg(rel_emb + r * DIMK + lane)
                     + ub * __ldg(rel_emb + r * DIMK + lane + 32);
            #pragma unroll
            for (int off = 16; off > 0; off >>= 1)
                pp += __shfl_xor_sync(0xffffffffu, pp, off);
            if (lane == 0) p.urel[r] = pp;
        }
    }
    __syncthreads();

    // ---- P2: softmax via half-warp butterflies (both items) ----
    #pragma unroll
    for (int ii = 0; ii < NITEMS; ++ii) {
        PerItem& p = s.pi[ii];
        float sc = p.urel[p.r2[tid]];
        float mx = sc;
        #pragma unroll
        for (int off = 8; off > 0; off >>= 1)
            mx = fmaxf(mx, __shfl_xor_sync(0xffffffffu, mx, off));
        float e = __expf(sc - mx);
        float sum = e;
        #pragma unroll
        for (int off = 8; off > 0; off >>= 1)
            sum += __shfl_xor_sync(0xffffffffu, sum, off);
        p.attn[tid] = __fdividef(e, sum);

        if (warp == ii) {   // hop-0 softmax on warp ii
            float sc0 = p.urel[p.r1[lane & 15]];
            float m0 = sc0;
            #pragma unroll
            for (int off = 8; off > 0; off >>= 1)
                m0 = fmaxf(m0, __shfl_xor_sync(0xffffffffu, m0, off));
            float e0 = __expf(sc0 - m0);
            float s0 = e0;
            #pragma unroll
            for (int off = 8; off > 0; off >>= 1)
                s0 += __shfl_xor_sync(0xffffffffu, s0, off);
            if (lane < 16) p.attn0[lane] = __fdividef(e0, s0);
        }
    }
    __syncthreads();

    // ---- P3: hop-1 aggregation (both items) + x0 on warps 6/7 ----
    #pragma unroll
    for (int ii = 0; ii < NITEMS; ++ii) {
        PerItem& p = s.pi[ii];
        const int m  = warp * 2 + (lane >> 4);
        const int l4 = lane & 15;
        const int4*   e2v = reinterpret_cast<const int4*>(p.e2 + m * NN);
        const float4* av  = reinterpret_cast<const float4*>(p.attn + m * NN);
        float4 acc = reinterpret_cast<const float4*>(p.e1v + m * DIMK)[l4];
        #pragma unroll
        for (int j = 0; j < 4; ++j) {
            const int4   ei = e2v[j];
            const float4 aw = av[j];
            const float4 v0 = __ldg(ent4 + ei.x * 16 + l4);
            const float4 v1 = __ldg(ent4 + ei.y * 16 + l4);
            const float4 v2 = __ldg(ent4 + ei.z * 16 + l4);
            const float4 v3 = __ldg(ent4 + ei.w * 16 + l4);
            acc.x = fmaf(aw.x, v0.x, acc.x); acc.y = fmaf(aw.x, v0.y, acc.y);
            acc.z = fmaf(aw.x, v0.z, acc.z); acc.w = fmaf(aw.x, v0.w, acc.w);
            acc.x = fmaf(aw.y, v1.x, acc.x); acc.y = fmaf(aw.y, v1.y, acc.y);
            acc.z = fmaf(aw.y, v1.z, acc.z); acc.w = fmaf(aw.y, v1.w, acc.w);
            acc.x = fmaf(aw.z, v2.x, acc.x); acc.y = fmaf(aw.z, v2.y, acc.y);
            acc.z = fmaf(aw.z, v2.z, acc.z); acc.w = fmaf(aw.z, v2.w, acc.w);
            acc.x = fmaf(aw.w, v3.x, acc.x); acc.y = fmaf(aw.w, v3.y, acc.y);
            acc.z = fmaf(aw.w, v3.z, acc.z); acc.w = fmaf(aw.w, v3.w, acc.w);
        }
        reinterpret_cast<float4*>(p.xbuf + m * DIMK)[l4] = acc;

        if (warp == 6 + ii && lane < 16) {   // x0 aggregation, one warp per item
            float4 a0 = reinterpret_cast<const float4*>(p.e0v)[lane];
            #pragma unroll
            for (int n = 0; n < NN; ++n) {
                const float4 ev = reinterpret_cast<const float4*>(p.e1v + n * DIMK)[lane];
                const float  an = p.attn0[n];
                a0.x = fmaf(an, ev.x, a0.x);
                a0.y = fmaf(an, ev.y, a0.y);
                a0.z = fmaf(an, ev.z, a0.z);
                a0.w = fmaf(an, ev.w, a0.w);
            }
            reinterpret_cast<float4*>(p.x0)[lane] = a0;
        }
    }
    __syncthreads();

    // ---- P4: fused GEMM (both items; h1 stays in registers; single-row loop
    //          to keep register pressure under the 7-CTA cap) ----
    #pragma unroll
    for (int ii = 0; ii < NITEMS; ++ii) {
        PerItem& p = s.pi[ii];
        const float b0c = s.b0[c];
        float x1acc = 0.f;
        #pragma unroll
        for (int r = 0; r < NN; ++r) {
            float a = 0.f;
            #pragma unroll
            for (int q = 0; q < 4; ++q) {
                const float4 xv = *reinterpret_cast<const float4*>(
                    p.xbuf + r * DIMK + kbase + q * 4);
                a = fmaf(xv.x, Wreg[q * 4 + 0], a);
                a = fmaf(xv.y, Wreg[q * 4 + 1], a);
                a = fmaf(xv.z, Wreg[q * 4 + 2], a);
                a = fmaf(xv.w, Wreg[q * 4 + 3], a);
            }
            a += __shfl_xor_sync(0xffffffffu, a, 8);
            a += __shfl_xor_sync(0xffffffffu, a, 16);
            if (kh0)
                x1acc = fmaf(p.attn0[r], fsigmoid(a + b0c), x1acc);
        }
        float a16 = 0.f;
        #pragma unroll
        for (int q = 0; q < 4; ++q) {
            const float4 xv = *reinterpret_cast<const float4*>(p.x0 + kbase + q * 4);
            a16 = fmaf(xv.x, Wreg[q * 4 + 0], a16);
            a16 = fmaf(xv.y, Wreg[q * 4 + 1], a16);
            a16 = fmaf(xv.z, Wreg[q * 4 + 2], a16);
            a16 = fmaf(xv.w, Wreg[q * 4 + 3], a16);
        }
        a16 += __shfl_xor_sync(0xffffffffu, a16, 8);
        a16 += __shfl_xor_sync(0xffffffffu, a16, 16);
        if (kh0) p.x1[c] = x1acc + fsigmoid(a16 + b0c);
    }
    __syncthreads();

    // ---- P5: final GEMM (W1 via L1-cached ldg) + tanh (both items) ----
    #pragma unroll
    for (int ii = 0; ii < NITEMS; ++ii) {
        PerItem& p = s.pi[ii];
        float acc = 0.f;
        #pragma unroll
        for (int kk = 0; kk < 16; ++kk) {
            const int k = kbase + kk;
            acc = fmaf(p.x1[k], __ldg(W1g + k * DIMK + c), acc);
        }
        acc += __shfl_xor_sync(0xffffffffu, acc, 8);
        acc += __shfl_xor_sync(0xffffffffu, acc, 16);
        if (kh0) p.outf[c] = tanhf(acc + s.b1[c]);
    }
    __syncthreads();

    // ---- P6: sigmoid(user . item), one warp per item ----
    if (warp < NITEMS) {
        PerItem& p = s.pi[warp];
        float pp = p.userv[lane] * p.outf[lane] + p.userv[lane + 32] * p.outf[lane + 32];
        #pragma unroll
        for (int off = 16; off > 0; off >>= 1)
            pp += __shfl_xor_sync(0xffffffffu, pp, off);
        if (lane == 0) out[item0 + warp] = fsigmoid(pp);
    }
}

extern "C" void kernel_launch(void* const* d_in, const int* in_sizes, int n_in,
                              void* d_out, int out_size) {
    const int*   u       = (const int*)d_in[0];
    const int*   v       = (const int*)d_in[1];
    const int*   adj     = (const int*)d_in[2];
    const int*   rel_adj = (const int*)d_in[3];
    const float* usr_emb = (const float*)d_in[4];
    const float* ent_emb = (const float*)d_in[5];
    const float* rel_emb = (const float*)d_in[6];
    const float* W0      = (const float*)d_in[7];
    const float* b0      = (const float*)d_in[8];
    const float* W1      = (const float*)d_in[9];
    const float* b1      = (const float*)d_in[10];
    float* outp = (float*)d_out;

    const int smem = (int)sizeof(Smem);
    cudaFuncSetAttribute(kgnn_kernel, cudaFuncAttributeMaxDynamicSharedMemorySize, smem);
    kgnn_kernel<<<GRID, NT, smem>>>(u, v, adj, rel_adj, usr_emb, ent_emb, rel_emb,
                                    W0, b0, W1, b1, outp);
}

// round 11
// speedup vs baseline: 1.1193x; 1.1193x over previous
#include <cuda_runtime.h>
#include <math.h>
#include <stdint.h>

#define DIMK 64
#define NN 16
#define BATCH 4096
#define NRELS 33
#define NT 256
#define NITEMS 2
#define GRID (BATCH / NITEMS)

struct PerItem {
    float e1v[NN * DIMK];     // 4 KB
    float xbuf[NN * DIMK];    // 4 KB
    float userv[DIMK];
    float e0v[DIMK];
    float x0[DIMK];
    float x1[DIMK];
    float outf[DIMK];
    float attn[NN * NN];      // 1 KB
    float urel[NRELS + 3];
    float attn0[NN];
    int   e2[NN * NN];        // 1 KB
    int   r2[NN * NN];        // 1 KB
    int   r1[NN];
};

struct Smem {
    PerItem pi[NITEMS];
    float b0[DIMK];
    float b1[DIMK];
};

__device__ __forceinline__ float fsigmoid(float x) {
    return __fdividef(1.0f, 1.0f + __expf(-x));
}

// packed-pair FMA: d = a*b + c elementwise on (lo,hi) f32 pairs
__device__ __forceinline__ uint64_t fma2(uint64_t a, uint64_t b, uint64_t c) {
    uint64_t d;
    asm("fma.rn.f32x2 %0, %1, %2, %3;" : "=l"(d) : "l"(a), "l"(b), "l"(c));
    return d;
}
__device__ __forceinline__ uint64_t pack2(float lo, float hi) {
    uint64_t d;
    asm("mov.b64 %0, {%1, %2};" : "=l"(d) : "f"(lo), "f"(hi));
    return d;
}
__device__ __forceinline__ float hadd2(uint64_t a) {
    float lo, hi;
    asm("mov.b64 {%0, %1}, %2;" : "=f"(lo), "=f"(hi) : "l"(a));
    return lo + hi;
}

__global__ __launch_bounds__(NT, 6)
void kgnn_kernel(const int* __restrict__ u, const int* __restrict__ v,
                 const int* __restrict__ adj, const int* __restrict__ rel_adj,
                 const float* __restrict__ usr_emb, const float* __restrict__ ent_emb,
                 const float* __restrict__ rel_emb,
                 const float* __restrict__ W0g, const float* __restrict__ b0g,
                 const float* __restrict__ W1g, const float* __restrict__ b1g,
                 float* __restrict__ out)
{
    extern __shared__ char smem_raw[];
    Smem& s = *reinterpret_cast<Smem*>(smem_raw);
    const int tid  = threadIdx.x;
    const int lane = tid & 31;
    const int warp = tid >> 5;
    const int c     = warp * 8 + (lane & 7);  // output column 0..63
    const int kh    = lane >> 3;              // k-quarter 0..3
    const int kbase = kh * 16;
    const bool kh0  = (kh == 0);

    const float4* ent4 = reinterpret_cast<const float4*>(ent_emb);
    const ulonglong2* ent8 = reinterpret_cast<const ulonglong2*>(ent_emb);
    const int item0 = blockIdx.x * NITEMS;

    // W0 column-slice in registers as packed pairs (consecutive k), once per CTA
    uint64_t Wp[8];
    #pragma unroll
    for (int q = 0; q < 8; ++q)
        Wp[q] = pack2(__ldg(W0g + (kbase + 2 * q) * DIMK + c),
                      __ldg(W0g + (kbase + 2 * q + 1) * DIMK + c));
    if (tid < DIMK) { s.b0[tid] = b0g[tid]; s.b1[tid] = b1g[tid]; }
    __syncthreads();

    // ---- P1: indices + e1v staging + root vectors + urel (both items) ----
    #pragma unroll
    for (int ii = 0; ii < NITEMS; ++ii) {
        PerItem& p = s.pi[ii];
        const int vv = __ldg(v + item0 + ii);
        const int uu = __ldg(u + item0 + ii);
        const int m = tid >> 4, n = tid & 15;
        const int e1m = __ldg(adj + vv * NN + m);
        p.e2[tid] = __ldg(adj + e1m * NN + n);
        p.r2[tid] = __ldg(rel_adj + e1m * NN + n);
        reinterpret_cast<float4*>(p.e1v)[tid] = __ldg(ent4 + e1m * 16 + n);
        if (tid < 16) {
            p.r1[tid] = __ldg(rel_adj + vv * NN + tid);
            reinterpret_cast<float4*>(p.userv)[tid] = __ldg(
                reinterpret_cast<const float4*>(usr_emb) + uu * 16 + tid);
        } else if (tid < 32) {
            reinterpret_cast<float4*>(p.e0v)[tid - 16] = __ldg(ent4 + vv * 16 + (tid - 16));
        }
        const float ua = __ldg(usr_emb + uu * DIMK + lane);
        const float ub = __ldg(usr_emb + uu * DIMK + lane + 32);
        for (int r = warp; r < NRELS; r += 8) {
            float pp = ua * __ldg(rel_emb + r * DIMK + lane)
                     + ub * __ldg(rel_emb + r * DIMK + lane + 32);
            #pragma unroll
            for (int off = 16; off > 0; off >>= 1)
                pp += __shfl_xor_sync(0xffffffffu, pp, off);
            if (lane == 0) p.urel[r] = pp;
        }
    }
    __syncthreads();

    // ---- P2: softmax via half-warp butterflies (both items) ----
    #pragma unroll
    for (int ii = 0; ii < NITEMS; ++ii) {
        PerItem& p = s.pi[ii];
        float sc = p.urel[p.r2[tid]];
        float mx = sc;
        #pragma unroll
        for (int off = 8; off > 0; off >>= 1)
            mx = fmaxf(mx, __shfl_xor_sync(0xffffffffu, mx, off));
        float e = __expf(sc - mx);
        float sum = e;
        #pragma unroll
        for (int off = 8; off > 0; off >>= 1)
            sum += __shfl_xor_sync(0xffffffffu, sum, off);
        p.attn[tid] = __fdividef(e, sum);

        if (warp == ii) {   // hop-0 softmax on warp ii
            float sc0 = p.urel[p.r1[lane & 15]];
            float m0 = sc0;
            #pragma unroll
            for (int off = 8; off > 0; off >>= 1)
                m0 = fmaxf(m0, __shfl_xor_sync(0xffffffffu, m0, off));
            float e0 = __expf(sc0 - m0);
            float s0 = e0;
            #pragma unroll
            for (int off = 8; off > 0; off >>= 1)
                s0 += __shfl_xor_sync(0xffffffffu, s0, off);
            if (lane < 16) p.attn0[lane] = __fdividef(e0, s0);
        }
    }
    __syncthreads();

    // ---- P3: hop-1 aggregation with packed FMA (both items) + x0 on warps 6/7 ----
    #pragma unroll
    for (int ii = 0; ii < NITEMS; ++ii) {
        PerItem& p = s.pi[ii];
        const int m  = warp * 2 + (lane >> 4);
        const int l4 = lane & 15;
        const int4*   e2v = reinterpret_cast<const int4*>(p.e2 + m * NN);
        const float4* av  = reinterpret_cast<const float4*>(p.attn + m * NN);
        ulonglong2 acc = reinterpret_cast<const ulonglong2*>(p.e1v + m * DIMK)[l4];
        #pragma unroll
        for (int j = 0; j < 4; ++j) {
            const int4   ei = e2v[j];
            const float4 aw = av[j];
            const uint64_t a0 = pack2(aw.x, aw.x);
            const uint64_t a1 = pack2(aw.y, aw.y);
            const uint64_t a2 = pack2(aw.z, aw.z);
            const uint64_t a3 = pack2(aw.w, aw.w);
            const ulonglong2 v0 = __ldg(ent8 + ei.x * 16 + l4);
            const ulonglong2 v1 = __ldg(ent8 + ei.y * 16 + l4);
            const ulonglong2 v2 = __ldg(ent8 + ei.z * 16 + l4);
            const ulonglong2 v3 = __ldg(ent8 + ei.w * 16 + l4);
            acc.x = fma2(a0, v0.x, acc.x); acc.y = fma2(a0, v0.y, acc.y);
            acc.x = fma2(a1, v1.x, acc.x); acc.y = fma2(a1, v1.y, acc.y);
            acc.x = fma2(a2, v2.x, acc.x); acc.y = fma2(a2, v2.y, acc.y);
            acc.x = fma2(a3, v3.x, acc.x); acc.y = fma2(a3, v3.y, acc.y);
        }
        reinterpret_cast<ulonglong2*>(p.xbuf + m * DIMK)[l4] = acc;

        if (warp == 6 + ii && lane < 16) {   // x0 aggregation, one warp per item
            ulonglong2 a0v = reinterpret_cast<const ulonglong2*>(p.e0v)[lane];
            #pragma unroll
            for (int n = 0; n < NN; ++n) {
                const ulonglong2 ev = reinterpret_cast<const ulonglong2*>(p.e1v + n * DIMK)[lane];
                const float an = p.attn0[n];
                const uint64_t an2 = pack2(an, an);
                a0v.x = fma2(an2, ev.x, a0v.x);
                a0v.y = fma2(an2, ev.y, a0v.y);
            }
            reinterpret_cast<ulonglong2*>(p.x0)[lane] = a0v;
        }
    }
    __syncthreads();

    // ---- P4: fused GEMM with packed FMA (both items; h1 stays in registers) ----
    #pragma unroll
    for (int ii = 0; ii < NITEMS; ++ii) {
        PerItem& p = s.pi[ii];
        const float b0c = s.b0[c];
        float x1acc = 0.f;
        #pragma unroll
        for (int r = 0; r < NN; r += 2) {
            uint64_t p0 = 0, p1 = 0;
            const ulonglong2* xr0 = reinterpret_cast<const ulonglong2*>(
                p.xbuf + r * DIMK + kbase);
            const ulonglong2* xr1 = reinterpret_cast<const ulonglong2*>(
                p.xbuf + (r + 1) * DIMK + kbase);
            #pragma unroll
            for (int q = 0; q < 4; ++q) {
                const ulonglong2 xv0 = xr0[q];
                const ulonglong2 xv1 = xr1[q];
                p0 = fma2(xv0.x, Wp[2 * q + 0], p0);
                p1 = fma2(xv1.x, Wp[2 * q + 0], p1);
                p0 = fma2(xv0.y, Wp[2 * q + 1], p0);
                p1 = fma2(xv1.y, Wp[2 * q + 1], p1);
            }
            float a0 = hadd2(p0);
            float a1 = hadd2(p1);
            a0 += __shfl_xor_sync(0xffffffffu, a0, 8);
            a1 += __shfl_xor_sync(0xffffffffu, a1, 8);
            a0 += __shfl_xor_sync(0xffffffffu, a0, 16);
            a1 += __shfl_xor_sync(0xffffffffu, a1, 16);
            if (kh0) {
                x1acc = fmaf(p.attn0[r],     fsigmoid(a0 + b0c), x1acc);
                x1acc = fmaf(p.attn0[r + 1], fsigmoid(a1 + b0c), x1acc);
            }
        }
        // x0 row -> out0 folded into x1
        uint64_t p16 = 0;
        const ulonglong2* x0r = reinterpret_cast<const ulonglong2*>(p.x0 + kbase);
        #pragma unroll
        for (int q = 0; q < 4; ++q) {
            const ulonglong2 xv = x0r[q];
            p16 = fma2(xv.x, Wp[2 * q + 0], p16);
            p16 = fma2(xv.y, Wp[2 * q + 1], p16);
        }
        float a16 = hadd2(p16);
        a16 += __shfl_xor_sync(0xffffffffu, a16, 8);
        a16 += __shfl_xor_sync(0xffffffffu, a16, 16);
        if (kh0) p.x1[c] = x1acc + fsigmoid(a16 + b0c);
    }
    __syncthreads();

    // ---- P5: final GEMM (W1 via L1-cached ldg) + tanh (both items) ----
    #pragma unroll
    for (int ii = 0; ii < NITEMS; ++ii) {
        PerItem& p = s.pi[ii];
        float acc = 0.f;
        #pragma unroll
        for (int kk = 0; kk < 16; ++kk) {
            const int k = kbase + kk;
            acc = fmaf(p.x1[k], __ldg(W1g + k * DIMK + c), acc);
        }
        acc += __shfl_xor_sync(0xffffffffu, acc, 8);
        acc += __shfl_xor_sync(0xffffffffu, acc, 16);
        if (kh0) p.outf[c] = tanhf(acc + s.b1[c]);
    }
    __syncthreads();

    // ---- P6: sigmoid(user . item), one warp per item ----
    if (warp < NITEMS) {
        PerItem& p = s.pi[warp];
        float pp = p.userv[lane] * p.outf[lane] + p.userv[lane + 32] * p.outf[lane + 32];
        #pragma unroll
        for (int off = 16; off > 0; off >>= 1)
            pp += __shfl_xor_sync(0xffffffffu, pp, off);
        if (lane == 0) out[item0 + warp] = fsigmoid(pp);
    }
}

extern "C" void kernel_launch(void* const* d_in, const int* in_sizes, int n_in,
                              void* d_out, int out_size) {
    const int*   u       = (const int*)d_in[0];
    const int*   v       = (const int*)d_in[1];
    const int*   adj     = (const int*)d_in[2];
    const int*   rel_adj = (const int*)d_in[3];
    const float* usr_emb = (const float*)d_in[4];
    const float* ent_emb = (const float*)d_in[5];
    const float* rel_emb = (const float*)d_in[6];
    const float* W0      = (const float*)d_in[7];
    const float* b0      = (const float*)d_in[8];
    const float* W1      = (const float*)d_in[9];
    const float* b1      = (const float*)d_in[10];
    float* outp = (float*)d_out;

    const int smem = (int)sizeof(Smem);
    cudaFuncSetAttribute(kgnn_kernel, cudaFuncAttributeMaxDynamicSharedMemorySize, smem);
    kgnn_kernel<<<GRID, NT, smem>>>(u, v, adj, rel_adj, usr_emb, ent_emb, rel_emb,
                                    W0, b0, W1, b1, outp);
}

// round 12
// speedup vs baseline: 1.1302x; 1.0097x over previous
#include <cuda_runtime.h>
#include <math.h>
#include <stdint.h>

#define DIMK 64
#define NN 16
#define BATCH 4096
#define NRELS 33
#define NT 256
#define NITEMS 2
#define GRID (BATCH / NITEMS)

struct PerItem {
    float e1v[NN * DIMK];     // 4 KB
    float xbuf[NN * DIMK];    // 4 KB
    float userv[DIMK];
    float e0v[DIMK];
    float x0[DIMK];
    float x1[DIMK];
    float outf[DIMK];
    float attn[NN * NN];      // 1 KB
    float urel[NRELS + 3];
    float attn0[NN];
    int   e2[NN * NN];        // 1 KB
    int   r2[NN * NN];        // 1 KB
    int   r1[NN];
};

struct Smem {
    PerItem pi[NITEMS];
    float b0[DIMK];
    float b1[DIMK];
};

__device__ __forceinline__ float fsigmoid(float x) {
    return __fdividef(1.0f, 1.0f + __expf(-x));
}

// packed-pair FMA: d = a*b + c elementwise on (lo,hi) f32 pairs
__device__ __forceinline__ uint64_t fma2(uint64_t a, uint64_t b, uint64_t c) {
    uint64_t d;
    asm("fma.rn.f32x2 %0, %1, %2, %3;" : "=l"(d) : "l"(a), "l"(b), "l"(c));
    return d;
}
__device__ __forceinline__ uint64_t pack2(float lo, float hi) {
    uint64_t d;
    asm("mov.b64 %0, {%1, %2};" : "=l"(d) : "f"(lo), "f"(hi));
    return d;
}
__device__ __forceinline__ float hadd2(uint64_t a) {
    float lo, hi;
    asm("mov.b64 {%0, %1}, %2;" : "=f"(lo), "=f"(hi) : "l"(a));
    return lo + hi;
}

__global__ __launch_bounds__(NT, 6)
void kgnn_kernel(const int* __restrict__ u, const int* __restrict__ v,
                 const int* __restrict__ adj, const int* __restrict__ rel_adj,
                 const float* __restrict__ usr_emb, const float* __restrict__ ent_emb,
                 const float* __restrict__ rel_emb,
                 const float* __restrict__ W0g, const float* __restrict__ b0g,
                 const float* __restrict__ W1g, const float* __restrict__ b1g,
                 float* __restrict__ out)
{
    extern __shared__ char smem_raw[];
    Smem& s = *reinterpret_cast<Smem*>(smem_raw);
    const int tid  = threadIdx.x;
    const int lane = tid & 31;
    const int warp = tid >> 5;
    const int c     = warp * 8 + (lane & 7);  // output column 0..63
    const int kh    = lane >> 3;              // k-quarter 0..3
    const int kbase = kh * 16;
    const bool kh0  = (kh == 0);

    const float4* ent4 = reinterpret_cast<const float4*>(ent_emb);
    const ulonglong2* ent8 = reinterpret_cast<const ulonglong2*>(ent_emb);
    const int item0 = blockIdx.x * NITEMS;

    // W0 column-slice in registers as packed pairs (consecutive k), once per CTA.
    // The SAME register array is later reloaded with W1 (W0 dead after P4).
    uint64_t Wp[8];
    #pragma unroll
    for (int q = 0; q < 8; ++q)
        Wp[q] = pack2(__ldg(W0g + (kbase + 2 * q) * DIMK + c),
                      __ldg(W0g + (kbase + 2 * q + 1) * DIMK + c));
    if (tid < DIMK) { s.b0[tid] = b0g[tid]; s.b1[tid] = b1g[tid]; }
    __syncthreads();

    // ---- P1: indices + e1v staging + root vectors + urel (both items) ----
    #pragma unroll
    for (int ii = 0; ii < NITEMS; ++ii) {
        PerItem& p = s.pi[ii];
        const int vv = __ldg(v + item0 + ii);
        const int uu = __ldg(u + item0 + ii);
        const int m = tid >> 4, n = tid & 15;
        const int e1m = __ldg(adj + vv * NN + m);
        p.e2[tid] = __ldg(adj + e1m * NN + n);
        p.r2[tid] = __ldg(rel_adj + e1m * NN + n);
        reinterpret_cast<float4*>(p.e1v)[tid] = __ldg(ent4 + e1m * 16 + n);
        if (tid < 16) {
            p.r1[tid] = __ldg(rel_adj + vv * NN + tid);
            reinterpret_cast<float4*>(p.userv)[tid] = __ldg(
                reinterpret_cast<const float4*>(usr_emb) + uu * 16 + tid);
        } else if (tid < 32) {
            reinterpret_cast<float4*>(p.e0v)[tid - 16] = __ldg(ent4 + vv * 16 + (tid - 16));
        }
        const float ua = __ldg(usr_emb + uu * DIMK + lane);
        const float ub = __ldg(usr_emb + uu * DIMK + lane + 32);
        for (int r = warp; r < NRELS; r += 8) {
            float pp = ua * __ldg(rel_emb + r * DIMK + lane)
                     + ub * __ldg(rel_emb + r * DIMK + lane + 32);
            #pragma unroll
            for (int off = 16; off > 0; off >>= 1)
                pp += __shfl_xor_sync(0xffffffffu, pp, off);
            if (lane == 0) p.urel[r] = pp;
        }
    }
    __syncthreads();

    // ---- P2: softmax via half-warp butterflies (both items) ----
    #pragma unroll
    for (int ii = 0; ii < NITEMS; ++ii) {
        PerItem& p = s.pi[ii];
        float sc = p.urel[p.r2[tid]];
        float mx = sc;
        #pragma unroll
        for (int off = 8; off > 0; off >>= 1)
            mx = fmaxf(mx, __shfl_xor_sync(0xffffffffu, mx, off));
        float e = __expf(sc - mx);
        float sum = e;
        #pragma unroll
        for (int off = 8; off > 0; off >>= 1)
            sum += __shfl_xor_sync(0xffffffffu, sum, off);
        p.attn[tid] = __fdividef(e, sum);

        if (warp == ii) {   // hop-0 softmax on warp ii
            float sc0 = p.urel[p.r1[lane & 15]];
            float m0 = sc0;
            #pragma unroll
            for (int off = 8; off > 0; off >>= 1)
                m0 = fmaxf(m0, __shfl_xor_sync(0xffffffffu, m0, off));
            float e0 = __expf(sc0 - m0);
            float s0 = e0;
            #pragma unroll
            for (int off = 8; off > 0; off >>= 1)
                s0 += __shfl_xor_sync(0xffffffffu, s0, off);
            if (lane < 16) p.attn0[lane] = __fdividef(e0, s0);
        }
    }
    __syncthreads();

    // ---- P3: hop-1 aggregation with packed FMA (both items) + x0 on warps 6/7 ----
    #pragma unroll
    for (int ii = 0; ii < NITEMS; ++ii) {
        PerItem& p = s.pi[ii];
        const int m  = warp * 2 + (lane >> 4);
        const int l4 = lane & 15;
        const int4*   e2v = reinterpret_cast<const int4*>(p.e2 + m * NN);
        const float4* av  = reinterpret_cast<const float4*>(p.attn + m * NN);
        ulonglong2 acc = reinterpret_cast<const ulonglong2*>(p.e1v + m * DIMK)[l4];
        #pragma unroll
        for (int j = 0; j < 4; ++j) {
            const int4   ei = e2v[j];
            const float4 aw = av[j];
            const uint64_t a0 = pack2(aw.x, aw.x);
            const uint64_t a1 = pack2(aw.y, aw.y);
            const uint64_t a2 = pack2(aw.z, aw.z);
            const uint64_t a3 = pack2(aw.w, aw.w);
            const ulonglong2 v0 = __ldg(ent8 + ei.x * 16 + l4);
            const ulonglong2 v1 = __ldg(ent8 + ei.y * 16 + l4);
            const ulonglong2 v2 = __ldg(ent8 + ei.z * 16 + l4);
            const ulonglong2 v3 = __ldg(ent8 + ei.w * 16 + l4);
            acc.x = fma2(a0, v0.x, acc.x); acc.y = fma2(a0, v0.y, acc.y);
            acc.x = fma2(a1, v1.x, acc.x); acc.y = fma2(a1, v1.y, acc.y);
            acc.x = fma2(a2, v2.x, acc.x); acc.y = fma2(a2, v2.y, acc.y);
            acc.x = fma2(a3, v3.x, acc.x); acc.y = fma2(a3, v3.y, acc.y);
        }
        reinterpret_cast<ulonglong2*>(p.xbuf + m * DIMK)[l4] = acc;

        if (warp == 6 + ii && lane < 16) {   // x0 aggregation, one warp per item
            ulonglong2 a0v = reinterpret_cast<const ulonglong2*>(p.e0v)[lane];
            #pragma unroll
            for (int n = 0; n < NN; ++n) {
                const ulonglong2 ev = reinterpret_cast<const ulonglong2*>(p.e1v + n * DIMK)[lane];
                const float an = p.attn0[n];
                const uint64_t an2 = pack2(an, an);
                a0v.x = fma2(an2, ev.x, a0v.x);
                a0v.y = fma2(an2, ev.y, a0v.y);
            }
            reinterpret_cast<ulonglong2*>(p.x0)[lane] = a0v;
        }
    }
    __syncthreads();

    // ---- P4: fused GEMM with packed FMA (both items; h1 stays in registers) ----
    #pragma unroll
    for (int ii = 0; ii < NITEMS; ++ii) {
        PerItem& p = s.pi[ii];
        const float b0c = s.b0[c];
        float x1acc = 0.f;
        #pragma unroll
        for (int r = 0; r < NN; r += 2) {
            uint64_t p0 = 0, p1 = 0;
            const ulonglong2* xr0 = reinterpret_cast<const ulonglong2*>(
                p.xbuf + r * DIMK + kbase);
            const ulonglong2* xr1 = reinterpret_cast<const ulonglong2*>(
                p.xbuf + (r + 1) * DIMK + kbase);
            #pragma unroll
            for (int q = 0; q < 4; ++q) {
                const ulonglong2 xv0 = xr0[q];
                const ulonglong2 xv1 = xr1[q];
                p0 = fma2(xv0.x, Wp[2 * q + 0], p0);
                p1 = fma2(xv1.x, Wp[2 * q + 0], p1);
                p0 = fma2(xv0.y, Wp[2 * q + 1], p0);
                p1 = fma2(xv1.y, Wp[2 * q + 1], p1);
            }
            float a0 = hadd2(p0);
            float a1 = hadd2(p1);
            a0 += __shfl_xor_sync(0xffffffffu, a0, 8);
            a1 += __shfl_xor_sync(0xffffffffu, a1, 8);
            a0 += __shfl_xor_sync(0xffffffffu, a0, 16);
            a1 += __shfl_xor_sync(0xffffffffu, a1, 16);
            if (kh0) {
                x1acc = fmaf(p.attn0[r],     fsigmoid(a0 + b0c), x1acc);
                x1acc = fmaf(p.attn0[r + 1], fsigmoid(a1 + b0c), x1acc);
            }
        }
        // x0 row -> out0 folded into x1
        uint64_t p16 = 0;
        const ulonglong2* x0r = reinterpret_cast<const ulonglong2*>(p.x0 + kbase);
        #pragma unroll
        for (int q = 0; q < 4; ++q) {
            const ulonglong2 xv = x0r[q];
            p16 = fma2(xv.x, Wp[2 * q + 0], p16);
            p16 = fma2(xv.y, Wp[2 * q + 1], p16);
        }
        float a16 = hadd2(p16);
        a16 += __shfl_xor_sync(0xffffffffu, a16, 8);
        a16 += __shfl_xor_sync(0xffffffffu, a16, 16);
        if (kh0) p.x1[c] = x1acc + fsigmoid(a16 + b0c);
    }

    // ---- W0 is dead: reload the SAME packed registers with W1 (L1-hot) ----
    #pragma unroll
    for (int q = 0; q < 8; ++q)
        Wp[q] = pack2(__ldg(W1g + (kbase + 2 * q) * DIMK + c),
                      __ldg(W1g + (kbase + 2 * q + 1) * DIMK + c));
    __syncthreads();

    // ---- P5: final GEMM (W1 in registers, x1 via broadcast LDS) + tanh ----
    #pragma unroll
    for (int ii = 0; ii < NITEMS; ++ii) {
        PerItem& p = s.pi[ii];
        uint64_t pa = 0;
        const ulonglong2* x1r = reinterpret_cast<const ulonglong2*>(p.x1 + kbase);
        #pragma unroll
        for (int q = 0; q < 4; ++q) {
            const ulonglong2 xv = x1r[q];
            pa = fma2(xv.x, Wp[2 * q + 0], pa);
            pa = fma2(xv.y, Wp[2 * q + 1], pa);
        }
        float acc = hadd2(pa);
        acc += __shfl_xor_sync(0xffffffffu, acc, 8);
        acc += __shfl_xor_sync(0xffffffffu, acc, 16);
        if (kh0) p.outf[c] = tanhf(acc + s.b1[c]);
    }
    __syncthreads();

    // ---- P6: sigmoid(user . item), one warp per item ----
    if (warp < NITEMS) {
        PerItem& p = s.pi[warp];
        float pp = p.userv[lane] * p.outf[lane] + p.userv[lane + 32] * p.outf[lane + 32];
        #pragma unroll
        for (int off = 16; off > 0; off >>= 1)
            pp += __shfl_xor_sync(0xffffffffu, pp, off);
        if (lane == 0) out[item0 + warp] = fsigmoid(pp);
    }
}

extern "C" void kernel_launch(void* const* d_in, const int* in_sizes, int n_in,
                              void* d_out, int out_size) {
    const int*   u       = (const int*)d_in[0];
    const int*   v       = (const int*)d_in[1];
    const int*   adj     = (const int*)d_in[2];
    const int*   rel_adj = (const int*)d_in[3];
    const float* usr_emb = (const float*)d_in[4];
    const float* ent_emb = (const float*)d_in[5];
    const float* rel_emb = (const float*)d_in[6];
    const float* W0      = (const float*)d_in[7];
    const float* b0      = (const float*)d_in[8];
    const float* W1      = (const float*)d_in[9];
    const float* b1      = (const float*)d_in[10];
    float* outp = (float*)d_out;

    const int smem = (int)sizeof(Smem);
    cudaFuncSetAttribute(kgnn_kernel, cudaFuncAttributeMaxDynamicSharedMemorySize, smem);
    kgnn_kernel<<<GRID, NT, smem>>>(u, v, adj, rel_adj, usr_emb, ent_emb, rel_emb,
                                    W0, b0, W1, b1, outp);
}

// round 13
// speedup vs baseline: 1.1351x; 1.0044x over previous
#include <cuda_runtime.h>
#include <math.h>
#include <stdint.h>

#define DIMK 64
#define NN 16
#define BATCH 4096
#define NRELS 33
#define NT 256
#define NITEMS 2
#define GRID (BATCH / NITEMS)
#define RST 80   // swizzled row stride in floats (4 chunks x 80 bytes)

struct PerItem {
    float e1v[NN * DIMK];     // 4 KB
    float xbuf[NN * RST];     // 5 KB, swizzled: chunk (kh,q) at float off kh*20+q*4
    float x0[RST];
    float x1[RST];
    float userv[DIMK];
    float e0v[DIMK];
    float outf[DIMK];
    float attn[NN * NN];      // 1 KB
    float urel[NRELS + 3];
    float attn0[NN];
    int   e2[NN * NN];        // 1 KB
    int   r2[NN * NN];        // 1 KB
    int   r1[NN];
};

struct Smem {
    PerItem pi[NITEMS];
    float b0[DIMK];
    float b1[DIMK];
};

__device__ __forceinline__ float fsigmoid(float x) {
    return __fdividef(1.0f, 1.0f + __expf(-x));
}

__device__ __forceinline__ uint64_t fma2(uint64_t a, uint64_t b, uint64_t c) {
    uint64_t d;
    asm("fma.rn.f32x2 %0, %1, %2, %3;" : "=l"(d) : "l"(a), "l"(b), "l"(c));
    return d;
}
__device__ __forceinline__ uint64_t pack2(float lo, float hi) {
    uint64_t d;
    asm("mov.b64 %0, {%1, %2};" : "=l"(d) : "f"(lo), "f"(hi));
    return d;
}
__device__ __forceinline__ float hadd2(uint64_t a) {
    float lo, hi;
    asm("mov.b64 {%0, %1}, %2;" : "=f"(lo), "=f"(hi) : "l"(a));
    return lo + hi;
}

__global__ __launch_bounds__(NT, 6)
void kgnn_kernel(const int* __restrict__ u, const int* __restrict__ v,
                 const int* __restrict__ adj, const int* __restrict__ rel_adj,
                 const float* __restrict__ usr_emb, const float* __restrict__ ent_emb,
                 const float* __restrict__ rel_emb,
                 const float* __restrict__ W0g, const float* __restrict__ b0g,
                 const float* __restrict__ W1g, const float* __restrict__ b1g,
                 float* __restrict__ out)
{
    extern __shared__ char smem_raw[];
    Smem& s = *reinterpret_cast<Smem*>(smem_raw);
    const int tid  = threadIdx.x;
    const int lane = tid & 31;
    const int warp = tid >> 5;
    const int c     = warp * 8 + (lane & 7);  // output column 0..63
    const int kh    = lane >> 3;              // k-quarter 0..3
    const int kbase = kh * 16;
    const int kh20  = kh * 20;                // swizzled chunk base (floats)
    const bool kh0  = (kh == 0);

    const float4* ent4 = reinterpret_cast<const float4*>(ent_emb);
    const ulonglong2* ent8 = reinterpret_cast<const ulonglong2*>(ent_emb);
    const int item0 = blockIdx.x * NITEMS;

    // W0 column-slice packed; later reloaded with W1 (W0 dead after P4)
    uint64_t Wp[8];
    #pragma unroll
    for (int q = 0; q < 8; ++q)
        Wp[q] = pack2(__ldg(W0g + (kbase + 2 * q) * DIMK + c),
                      __ldg(W0g + (kbase + 2 * q + 1) * DIMK + c));
    if (tid < DIMK) { s.b0[tid] = b0g[tid]; s.b1[tid] = b1g[tid]; }
    __syncthreads();

    // ---- P1: indices + e1v staging + root vectors + urel (both items) ----
    #pragma unroll
    for (int ii = 0; ii < NITEMS; ++ii) {
        PerItem& p = s.pi[ii];
        const int vv = __ldg(v + item0 + ii);
        const int uu = __ldg(u + item0 + ii);
        const int m = tid >> 4, n = tid & 15;
        const int e1m = __ldg(adj + vv * NN + m);
        p.e2[tid] = __ldg(adj + e1m * NN + n);
        p.r2[tid] = __ldg(rel_adj + e1m * NN + n);
        reinterpret_cast<float4*>(p.e1v)[tid] = __ldg(ent4 + e1m * 16 + n);
        if (tid < 16) {
            p.r1[tid] = __ldg(rel_adj + vv * NN + tid);
            reinterpret_cast<float4*>(p.userv)[tid] = __ldg(
                reinterpret_cast<const float4*>(usr_emb) + uu * 16 + tid);
        } else if (tid < 32) {
            reinterpret_cast<float4*>(p.e0v)[tid - 16] = __ldg(ent4 + vv * 16 + (tid - 16));
        }
        const float ua = __ldg(usr_emb + uu * DIMK + lane);
        const float ub = __ldg(usr_emb + uu * DIMK + lane + 32);
        for (int r = warp; r < NRELS; r += 8) {
            float pp = ua * __ldg(rel_emb + r * DIMK + lane)
                     + ub * __ldg(rel_emb + r * DIMK + lane + 32);
            #pragma unroll
            for (int off = 16; off > 0; off >>= 1)
                pp += __shfl_xor_sync(0xffffffffu, pp, off);
            if (lane == 0) p.urel[r] = pp;
        }
    }
    __syncthreads();

    // ---- P2: softmax via half-warp butterflies (both items) ----
    #pragma unroll
    for (int ii = 0; ii < NITEMS; ++ii) {
        PerItem& p = s.pi[ii];
        float sc = p.urel[p.r2[tid]];
        float mx = sc;
        #pragma unroll
        for (int off = 8; off > 0; off >>= 1)
            mx = fmaxf(mx, __shfl_xor_sync(0xffffffffu, mx, off));
        float e = __expf(sc - mx);
        float sum = e;
        #pragma unroll
        for (int off = 8; off > 0; off >>= 1)
            sum += __shfl_xor_sync(0xffffffffu, sum, off);
        p.attn[tid] = __fdividef(e, sum);

        if (warp == ii) {
            float sc0 = p.urel[p.r1[lane & 15]];
            float m0 = sc0;
            #pragma unroll
            for (int off = 8; off > 0; off >>= 1)
                m0 = fmaxf(m0, __shfl_xor_sync(0xffffffffu, m0, off));
            float e0 = __expf(sc0 - m0);
            float s0 = e0;
            #pragma unroll
            for (int off = 8; off > 0; off >>= 1)
                s0 += __shfl_xor_sync(0xffffffffu, s0, off);
            if (lane < 16) p.attn0[lane] = __fdividef(e0, s0);
        }
    }
    __syncthreads();

    // ---- P3: hop-1 aggregation (both items) + x0 on warps 6/7; swizzled stores ----
    #pragma unroll
    for (int ii = 0; ii < NITEMS; ++ii) {
        PerItem& p = s.pi[ii];
        const int m  = warp * 2 + (lane >> 4);
        const int l4 = lane & 15;
        const int swoff = (l4 >> 2) * 20 + (l4 & 3) * 4;  // swizzled chunk offset
        const int4*   e2v = reinterpret_cast<const int4*>(p.e2 + m * NN);
        const float4* av  = reinterpret_cast<const float4*>(p.attn + m * NN);
        ulonglong2 acc = reinterpret_cast<const ulonglong2*>(p.e1v + m * DIMK)[l4];
        #pragma unroll
        for (int j = 0; j < 4; ++j) {
            const int4   ei = e2v[j];
            const float4 aw = av[j];
            const uint64_t a0 = pack2(aw.x, aw.x);
            const uint64_t a1 = pack2(aw.y, aw.y);
            const uint64_t a2 = pack2(aw.z, aw.z);
            const uint64_t a3 = pack2(aw.w, aw.w);
            const ulonglong2 v0 = __ldg(ent8 + ei.x * 16 + l4);
            const ulonglong2 v1 = __ldg(ent8 + ei.y * 16 + l4);
            const ulonglong2 v2 = __ldg(ent8 + ei.z * 16 + l4);
            const ulonglong2 v3 = __ldg(ent8 + ei.w * 16 + l4);
            acc.x = fma2(a0, v0.x, acc.x); acc.y = fma2(a0, v0.y, acc.y);
            acc.x = fma2(a1, v1.x, acc.x); acc.y = fma2(a1, v1.y, acc.y);
            acc.x = fma2(a2, v2.x, acc.x); acc.y = fma2(a2, v2.y, acc.y);
            acc.x = fma2(a3, v3.x, acc.x); acc.y = fma2(a3, v3.y, acc.y);
        }
        *reinterpret_cast<ulonglong2*>(p.xbuf + m * RST + swoff) = acc;

        if (warp == 6 + ii && lane < 16) {
            ulonglong2 a0v = reinterpret_cast<const ulonglong2*>(p.e0v)[lane];
            #pragma unroll
            for (int n = 0; n < NN; ++n) {
                const ulonglong2 ev = reinterpret_cast<const ulonglong2*>(p.e1v + n * DIMK)[lane];
                const float an = p.attn0[n];
                const uint64_t an2 = pack2(an, an);
                a0v.x = fma2(an2, ev.x, a0v.x);
                a0v.y = fma2(an2, ev.y, a0v.y);
            }
            *reinterpret_cast<ulonglong2*>(p.x0 + swoff) = a0v;
        }
    }
    __syncthreads();

    // ---- P4: fused GEMM, conflict-free swizzled x reads ----
    #pragma unroll
    for (int ii = 0; ii < NITEMS; ++ii) {
        PerItem& p = s.pi[ii];
        const float b0c = s.b0[c];
        float x1acc = 0.f;
        #pragma unroll
        for (int r = 0; r < NN; r += 2) {
            uint64_t p0 = 0, p1 = 0;
            const float* xr0 = p.xbuf + r * RST + kh20;
            const float* xr1 = p.xbuf + (r + 1) * RST + kh20;
            #pragma unroll
            for (int q = 0; q < 4; ++q) {
                const ulonglong2 xv0 = *reinterpret_cast<const ulonglong2*>(xr0 + q * 4);
                const ulonglong2 xv1 = *reinterpret_cast<const ulonglong2*>(xr1 + q * 4);
                p0 = fma2(xv0.x, Wp[2 * q + 0], p0);
                p1 = fma2(xv1.x, Wp[2 * q + 0], p1);
                p0 = fma2(xv0.y, Wp[2 * q + 1], p0);
                p1 = fma2(xv1.y, Wp[2 * q + 1], p1);
            }
            float a0 = hadd2(p0);
            float a1 = hadd2(p1);
            a0 += __shfl_xor_sync(0xffffffffu, a0, 8);
            a1 += __shfl_xor_sync(0xffffffffu, a1, 8);
            a0 += __shfl_xor_sync(0xffffffffu, a0, 16);
            a1 += __shfl_xor_sync(0xffffffffu, a1, 16);
            if (kh0) {
                x1acc = fmaf(p.attn0[r],     fsigmoid(a0 + b0c), x1acc);
                x1acc = fmaf(p.attn0[r + 1], fsigmoid(a1 + b0c), x1acc);
            }
        }
        uint64_t p16 = 0;
        const float* x0r = p.x0 + kh20;
        #pragma unroll
        for (int q = 0; q < 4; ++q) {
            const ulonglong2 xv = *reinterpret_cast<const ulonglong2*>(x0r + q * 4);
            p16 = fma2(xv.x, Wp[2 * q + 0], p16);
            p16 = fma2(xv.y, Wp[2 * q + 1], p16);
        }
        float a16 = hadd2(p16);
        a16 += __shfl_xor_sync(0xffffffffu, a16, 8);
        a16 += __shfl_xor_sync(0xffffffffu, a16, 16);
        if (kh0) p.x1[((c >> 4) * 20) + (c & 15)] = x1acc + fsigmoid(a16 + b0c);
    }

    // ---- W0 dead: reload the SAME packed registers with W1 ----
    #pragma unroll
    for (int q = 0; q < 8; ++q)
        Wp[q] = pack2(__ldg(W1g + (kbase + 2 * q) * DIMK + c),
                      __ldg(W1g + (kbase + 2 * q + 1) * DIMK + c));
    __syncthreads();

    // ---- P5: final GEMM (W1 in registers, swizzled x1) + tanh ----
    #pragma unroll
    for (int ii = 0; ii < NITEMS; ++ii) {
        PerItem& p = s.pi[ii];
        uint64_t pa = 0;
        const float* x1r = p.x1 + kh20;
        #pragma unroll
        for (int q = 0; q < 4; ++q) {
            const ulonglong2 xv = *reinterpret_cast<const ulonglong2*>(x1r + q * 4);
            pa = fma2(xv.x, Wp[2 * q + 0], pa);
            pa = fma2(xv.y, Wp[2 * q + 1], pa);
        }
        float acc = hadd2(pa);
        acc += __shfl_xor_sync(0xffffffffu, acc, 8);
        acc += __shfl_xor_sync(0xffffffffu, acc, 16);
        if (kh0) p.outf[c] = tanhf(acc + s.b1[c]);
    }
    __syncthreads();

    // ---- P6: sigmoid(user . item), one warp per item ----
    if (warp < NITEMS) {
        PerItem& p = s.pi[warp];
        float pp = p.userv[lane] * p.outf[lane] + p.userv[lane + 32] * p.outf[lane + 32];
        #pragma unroll
        for (int off = 16; off > 0; off >>= 1)
            pp += __shfl_xor_sync(0xffffffffu, pp, off);
        if (lane == 0) out[item0 + warp] = fsigmoid(pp);
    }
}

extern "C" void kernel_launch(void* const* d_in, const int* in_sizes, int n_in,
                              void* d_out, int out_size) {
    const int*   u       = (const int*)d_in[0];
    const int*   v       = (const int*)d_in[1];
    const int*   adj     = (const int*)d_in[2];
    const int*   rel_adj = (const int*)d_in[3];
    const float* usr_emb = (const float*)d_in[4];
    const float* ent_emb = (const float*)d_in[5];
    const float* rel_emb = (const float*)d_in[6];
    const float* W0      = (const float*)d_in[7];
    const float* b0      = (const float*)d_in[8];
    const float* W1      = (const float*)d_in[9];
    const float* b1      = (const float*)d_in[10];
    float* outp = (float*)d_out;

    const int smem = (int)sizeof(Smem);
    cudaFuncSetAttribute(kgnn_kernel, cudaFuncAttributeMaxDynamicSharedMemorySize, smem);
    kgnn_kernel<<<GRID, NT, smem>>>(u, v, adj, rel_adj, usr_emb, ent_emb, rel_emb,
                                    W0, b0, W1, b1, outp);
}